// round 7
// baseline (speedup 1.0000x reference)
#include <cuda_runtime.h>
#include <cuda_bf16.h>
#include <cstdint>

// Problem constants
#define NN   32
#define CC   512
#define HWL  3136        // 56*56
#define GG   8
#define LL   64
#define MTOT 100352      // NN*HWL
#define EPSV 1e-4f
#define NPART 128        // 32 n-chunks * 4 k-chunks
#define RL   68          // smem row length in floats (64 + 4 pad -> odd quad stride)

typedef unsigned long long ull;

// ---------------- scratch (device globals; no allocation allowed) -------------
__device__ float g_pcov[GG][NPART][LL * LL];  // partial Grams
__device__ float g_psum[GG][NPART][LL];       // partial channel sums
__device__ float g_mu[CC];
__device__ float g_cov[GG * LL * LL];
__device__ float g_subT[GG * LL * LL];        // whitening subspace, TRANSPOSED [g][k][i] = S[i][k]
__device__ float g_t[CC];                     // t[c] = sum_j S[c][j] * mu[g*64+j]

// ---------------- helpers ------------------------------------------------------
__device__ __forceinline__ uint32_t smem_u32(const void* p) {
    uint32_t a;
    asm("{ .reg .u64 t; cvta.to.shared.u64 t, %1; cvt.u32.u64 %0, t; }" : "=r"(a) : "l"(p));
    return a;
}
__device__ __forceinline__ void cpasync16(uint32_t dst, const void* src) {
    asm volatile("cp.async.ca.shared.global [%0], [%1], 16;" :: "r"(dst), "l"(src) : "memory");
}
#define CP_COMMIT() asm volatile("cp.async.commit_group;" ::: "memory")
#define CP_WAIT0()  asm volatile("cp.async.wait_group 0;" ::: "memory")

__device__ __forceinline__ ull ffma2(ull a, ull b, ull c) {
    ull d;
    asm("fma.rn.f32x2 %0, %1, %2, %3;" : "=l"(d) : "l"(a), "l"(b), "l"(c));
    return d;
}
__device__ __forceinline__ ull dup2(float v) {
    ull d;
    asm("mov.b64 %0, {%1, %1};" : "=l"(d) : "f"(v));
    return d;
}
__device__ __forceinline__ float2 unpack2(ull v) {
    float lo, hi;
    asm("mov.b64 {%0, %1}, %2;" : "=f"(lo), "=f"(hi) : "l"(v));
    return make_float2(lo, hi);
}

// =============================================================================
// Kernel 1: partial Gram + partial channel sums, k-pair FFMA2 (lanes = hw pair).
// grid (4 k-chunks, 32 n, 8 g), 64 threads. Thread tile: 16 a-rows (ag+4m) x
// 4 b-rows (bg4+16w). Smem tile = natural X[ch][hw] rows (no transpose),
// double-buffered via cp.async. Zero MOV overhead in the inner loop.
// =============================================================================
__global__ __launch_bounds__(64) void k_cov_partial(const float* __restrict__ x) {
    const int q = blockIdx.x;           // k-chunk 0..3
    const int n = blockIdx.y;
    const int g = blockIdx.z;
    __shared__ __align__(16) float Xs[2][64 * RL];   // 2 x 17408 B

    const int tid = threadIdx.x;
    const int ag  = tid & 3;            // a-row base (rows ag+4m)
    const int bg4 = (tid >> 2) & 15;    // b-row base (rows bg4+16w)

    const int tiles = (q == 0) ? 13 : 12;
    const int k0    = (q == 0) ? 0 : (832 + (q - 1) * 768);
    const float* base = x + ((size_t)n * CC + (size_t)g * LL) * HWL + k0;

    const uint32_t xs0 = smem_u32(&Xs[0][0]), xs1 = smem_u32(&Xs[1][0]);

    #define COV_ISSUE(dst, t) do {                                                  \
        _Pragma("unroll")                                                           \
        for (int idx = tid; idx < 1024; idx += 64) {                                \
            int r = idx >> 4, c = idx & 15;                                         \
            cpasync16((dst) + (uint32_t)(r * RL + c * 4) * 4,                       \
                      base + (size_t)r * HWL + (t) * 64 + c * 4);                   \
        }                                                                           \
        CP_COMMIT();                                                                \
    } while (0)

    ull acc[16][4];
    #pragma unroll
    for (int m = 0; m < 16; ++m)
        #pragma unroll
        for (int w = 0; w < 4; ++w) acc[m][w] = 0ull;
    float rowsum = 0.f;

    COV_ISSUE(xs0, 0);

    for (int tI = 0; tI < tiles; ++tI) {
        CP_WAIT0();
        __syncthreads();
        if (tI + 1 < tiles) COV_ISSUE((tI & 1) ? xs0 : xs1, tI + 1);

        const float* X = &Xs[tI & 1][0];
        #pragma unroll 4
        for (int k4 = 0; k4 < 16; ++k4) {
            // rowsum (channel tid)
            float4 rv = *reinterpret_cast<const float4*>(X + tid * RL + k4 * 4);
            rowsum += (rv.x + rv.y) + (rv.z + rv.w);

            ulonglong2 b[4];
            #pragma unroll
            for (int w = 0; w < 4; ++w)
                b[w] = *reinterpret_cast<const ulonglong2*>(X + (bg4 + 16 * w) * RL + k4 * 4);

            #pragma unroll
            for (int m = 0; m < 16; ++m) {
                ulonglong2 av = *reinterpret_cast<const ulonglong2*>(X + (ag + 4 * m) * RL + k4 * 4);
                #pragma unroll
                for (int w = 0; w < 4; ++w)
                    acc[m][w] = ffma2(av.x, b[w].x, ffma2(av.y, b[w].y, acc[m][w]));
            }
        }
        __syncthreads();
    }
    #undef COV_ISSUE

    const int p = n * 4 + q;
    g_psum[g][p][tid] = rowsum;
    float* outp = &g_pcov[g][p][0];
    #pragma unroll
    for (int m = 0; m < 16; ++m)
        #pragma unroll
        for (int w = 0; w < 4; ++w) {
            float2 f = unpack2(acc[m][w]);
            outp[(ag + 4 * m) * 64 + bg4 + 16 * w] = f.x + f.y;
        }
}

// =============================================================================
// Kernel 2a: reduce channel sums -> mu.  grid 8, 64 threads.
// =============================================================================
__global__ __launch_bounds__(64) void k_mean() {
    const int g = blockIdx.x, i = threadIdx.x;
    float s = 0.f;
    #pragma unroll 4
    for (int p = 0; p < NPART; ++p) s += g_psum[g][p][i];
    g_mu[g * LL + i] = s / (float)MTOT;
}

// =============================================================================
// Kernel 2b: reduce partial Grams -> cov (with -mu mu^T + eps I). grid (16,8).
// =============================================================================
__global__ __launch_bounds__(256) void k_cov_finalize() {
    const int g = blockIdx.y;
    const int e = blockIdx.x * 256 + threadIdx.x;
    const int i = e >> 6, j = e & 63;
    float s0 = 0.f, s1 = 0.f, s2 = 0.f, s3 = 0.f;
    #pragma unroll 4
    for (int p = 0; p < NPART; p += 4) {
        s0 += g_pcov[g][p + 0][e];
        s1 += g_pcov[g][p + 1][e];
        s2 += g_pcov[g][p + 2][e];
        s3 += g_pcov[g][p + 3][e];
    }
    float c = ((s0 + s1) + (s2 + s3)) / (float)MTOT - g_mu[g * LL + i] * g_mu[g * LL + j];
    if (i == j) c += EPSV;
    g_cov[g * LL * LL + e] = c;
}

// =============================================================================
// Kernel 3: power iteration + deflation (unchanged — matched reference in R1).
// =============================================================================
#define MATVEC64(res, Aarr, vptr) {                                        \
    float y0 = 0.f, y1 = 0.f, y2 = 0.f, y3 = 0.f;                          \
    _Pragma("unroll")                                                      \
    for (int j_ = 0; j_ < 64; j_ += 4) {                                   \
        y0 = fmaf(Aarr[j_ + 0], (vptr)[j_ + 0], y0);                       \
        y1 = fmaf(Aarr[j_ + 1], (vptr)[j_ + 1], y1);                       \
        y2 = fmaf(Aarr[j_ + 2], (vptr)[j_ + 2], y2);                       \
        y3 = fmaf(Aarr[j_ + 3], (vptr)[j_ + 3], y3);                       \
    }                                                                      \
    res = (y0 + y1) + (y2 + y3);                                           \
}

__device__ __forceinline__ float sumsq64(const float* v) {
    float y0 = 0.f, y1 = 0.f, y2 = 0.f, y3 = 0.f;
    #pragma unroll
    for (int j = 0; j < 64; j += 4) {
        y0 = fmaf(v[j + 0], v[j + 0], y0);
        y1 = fmaf(v[j + 1], v[j + 1], y1);
        y2 = fmaf(v[j + 2], v[j + 2], y2);
        y3 = fmaf(v[j + 3], v[j + 3], y3);
    }
    return (y0 + y1) + (y2 + y3);
}
__device__ __forceinline__ float dot64(const float* a, const float* b) {
    float y0 = 0.f, y1 = 0.f, y2 = 0.f, y3 = 0.f;
    #pragma unroll
    for (int j = 0; j < 64; j += 4) {
        y0 = fmaf(a[j + 0], b[j + 0], y0);
        y1 = fmaf(a[j + 1], b[j + 1], y1);
        y2 = fmaf(a[j + 2], b[j + 2], y2);
        y3 = fmaf(a[j + 3], b[j + 3], y3);
    }
    return (y0 + y1) + (y2 + y3);
}

__global__ __launch_bounds__(64) void k_pi(const float* __restrict__ vinit) {
    const int g = blockIdx.x, i = threadIdx.x;
    __shared__ float vs[2][64];
    __shared__ float av[64];

    float A[64], S[64];
    #pragma unroll
    for (int j = 0; j < 64; ++j) {
        A[j] = g_cov[g * LL * LL + i * 64 + j];
        S[j] = 0.f;
    }

    float lam_prev = 0.f;

    for (int e = 0; e < 64; ++e) {
        __syncthreads();
        vs[0][i] = vinit[((size_t)g * LL + e) * LL + i];
        __syncthreads();

        float n2  = sumsq64(vs[0]);
        float inv = 1.f / (sqrtf(n2) + 1e-12f);
        int cur = 0;

        #pragma unroll 1
        for (int it = 0; it < 19; ++it) {
            float y;
            MATVEC64(y, A, vs[cur]);
            y *= inv;
            vs[cur ^ 1][i] = y;
            __syncthreads();
            cur ^= 1;
            n2  = sumsq64(vs[cur]);
            inv = 1.f / (sqrtf(n2) + 1e-12f);
        }

        float vi = vs[cur][i] * inv;
        __syncthreads();
        vs[cur ^ 1][i] = vi;
        __syncthreads();
        cur ^= 1;

        float Avi;
        MATVEC64(Avi, A, vs[cur]);
        av[i] = Avi;
        __syncthreads();

        float vAv = dot64(vs[cur], av);
        float vv  = sumsq64(vs[cur]);
        float lam = vAv / vv;

        if (e > 0 && (lam_prev < lam || lam < EPSV)) break;

        float svi = rsqrtf(lam) * vi;
        #pragma unroll
        for (int j = 0; j < 64; ++j) {
            float vj = vs[cur][j];
            S[j] = fmaf(svi, vj, S[j]);
            A[j] = fmaf(-Avi, vj, A[j]);
        }
        lam_prev = lam;
    }

    #pragma unroll
    for (int j = 0; j < 64; ++j) g_subT[g * LL * LL + j * 64 + i] = S[j];

    float t = 0.f;
    #pragma unroll
    for (int j = 0; j < 64; ++j) t = fmaf(S[j], g_mu[g * LL + j], t);
    g_t[g * LL + i] = t;
}

// =============================================================================
// Kernel 4: apply whitening + affine, k-pair FFMA2 (lanes = two hw OUTPUTS).
// out = (S @ x) * w + (b - t*w).  grid (7 hw-chunks, 32 n, 8 g), 64 threads.
// Thread tile: 4 ch (chg+16u) x 16 hw (chunks hwg+4e). Sdup[k][i]=(s,s) table
// (32 KB smem, built once per block); X tiles natural rows, cp.async
// double-buffered. Inner loop: 32 FFMA2 + 4 LDS.64 + 4 LDS.128 per k.
// =============================================================================
#define AP_SMEM_BYTES (32768 + 2 * 64 * RL * 4)

__global__ __launch_bounds__(64) void k_apply(const float* __restrict__ x,
                                              const float* __restrict__ wgt,
                                              const float* __restrict__ bia,
                                              float* __restrict__ out) {
    extern __shared__ __align__(16) char smem[];
    ull*   Sd  = reinterpret_cast<ull*>(smem);                 // [64][64] dup pairs
    float* Xb0 = reinterpret_cast<float*>(smem + 32768);
    float* Xb1 = Xb0 + 64 * RL;

    const int hb = blockIdx.x;            // 0..6 (448 hw each)
    const int n  = blockIdx.y;
    const int g  = blockIdx.z;
    const int tid = threadIdx.x;
    const int chg = tid & 15;             // ch = chg + 16u
    const int hwg = tid >> 4;             // hw chunks = hwg + 4e

    const float* xbase = x   + ((size_t)n * CC + (size_t)g * LL) * HWL + hb * 448;
    float*       obase = out + ((size_t)n * CC + (size_t)g * LL) * HWL + hb * 448;

    const uint32_t xs0 = smem_u32(Xb0), xs1 = smem_u32(Xb1);

    #define AP_ISSUE(dst, t) do {                                                   \
        _Pragma("unroll")                                                           \
        for (int idx = tid; idx < 1024; idx += 64) {                                \
            int r = idx >> 4, c = idx & 15;                                         \
            cpasync16((dst) + (uint32_t)(r * RL + c * 4) * 4,                       \
                      xbase + (size_t)r * HWL + (t) * 64 + c * 4);                  \
        }                                                                           \
        CP_COMMIT();                                                                \
    } while (0)

    AP_ISSUE(xs0, 0);

    // build Sdup table: Sd[k*64+i] = (S[i][k], S[i][k]); g_subT[g][k*64+i]=S[i][k]
    {
        const float* src = g_subT + g * 4096;
        #pragma unroll
        for (int idx = tid; idx < 4096; idx += 64) Sd[idx] = dup2(src[idx]);
    }

    // epilogue constants, duplicated per channel
    ull wd[4], qd[4];
    #pragma unroll
    for (int u = 0; u < 4; ++u) {
        int c = g * LL + chg + 16 * u;
        float w = wgt[c];
        wd[u] = dup2(w);
        qd[u] = dup2(bia[c] - g_t[c] * w);
    }

    for (int t = 0; t < 7; ++t) {
        CP_WAIT0();
        __syncthreads();
        if (t < 6) AP_ISSUE((t & 1) ? xs0 : xs1, t + 1);

        const float* X = (t & 1) ? Xb1 : Xb0;
        ull acc[4][8];
        #pragma unroll
        for (int u = 0; u < 4; ++u)
            #pragma unroll
            for (int e = 0; e < 8; ++e) acc[u][e] = 0ull;

        #pragma unroll 4
        for (int k = 0; k < 64; ++k) {
            const ull* Srow = Sd + k * 64;
            ull a0 = Srow[chg], a1 = Srow[chg + 16], a2 = Srow[chg + 32], a3 = Srow[chg + 48];
            #pragma unroll
            for (int e = 0; e < 4; ++e) {
                ulonglong2 bv = *reinterpret_cast<const ulonglong2*>(X + k * RL + (hwg + 4 * e) * 4);
                acc[0][2*e]   = ffma2(a0, bv.x, acc[0][2*e]);
                acc[0][2*e+1] = ffma2(a0, bv.y, acc[0][2*e+1]);
                acc[1][2*e]   = ffma2(a1, bv.x, acc[1][2*e]);
                acc[1][2*e+1] = ffma2(a1, bv.y, acc[1][2*e+1]);
                acc[2][2*e]   = ffma2(a2, bv.x, acc[2][2*e]);
                acc[2][2*e+1] = ffma2(a2, bv.y, acc[2][2*e+1]);
                acc[3][2*e]   = ffma2(a3, bv.x, acc[3][2*e]);
                acc[3][2*e+1] = ffma2(a3, bv.y, acc[3][2*e+1]);
            }
        }

        // epilogue: out = acc * w + q, packed; store float4 per (u, e)
        #pragma unroll
        for (int u = 0; u < 4; ++u) {
            float* op = obase + (size_t)(chg + 16 * u) * HWL + t * 64;
            #pragma unroll
            for (int e = 0; e < 4; ++e) {
                ull r0 = ffma2(acc[u][2*e],   wd[u], qd[u]);
                ull r1 = ffma2(acc[u][2*e+1], wd[u], qd[u]);
                float2 f0 = unpack2(r0), f1 = unpack2(r1);
                float4 v = make_float4(f0.x, f0.y, f1.x, f1.y);
                *reinterpret_cast<float4*>(op + (hwg + 4 * e) * 4) = v;
            }
        }
        __syncthreads();
    }
    #undef AP_ISSUE
}

// =============================================================================
extern "C" void kernel_launch(void* const* d_in, const int* in_sizes, int n_in,
                              void* d_out, int out_size) {
    const float* x     = (const float*)d_in[0];
    const float* vinit = (const float*)d_in[1];
    const float* wgt   = (const float*)d_in[2];
    const float* bia   = (const float*)d_in[3];
    float* out = (float*)d_out;
    (void)in_sizes; (void)n_in; (void)out_size;

    cudaFuncSetAttribute(k_apply, cudaFuncAttributeMaxDynamicSharedMemorySize, AP_SMEM_BYTES);

    k_cov_partial<<<dim3(4, 32, 8), 64>>>(x);
    k_mean<<<8, 64>>>();
    k_cov_finalize<<<dim3(16, 8), 256>>>();
    k_pi<<<8, 64>>>(vinit);
    k_apply<<<dim3(7, 32, 8), 64, AP_SMEM_BYTES>>>(x, wgt, bia, out);
}